// round 1
// baseline (speedup 1.0000x reference)
#include <cuda_runtime.h>
#include <cuda_bf16.h>
#include <math.h>

#define NTOK 4096      // B*S = 2*2048
#define HDIM 1024
#define IDIM 3584
#define NEXP 8

// ---- device scratch (allocation-free: __device__ globals) ----
__device__ int   g_cnt[NEXP];
__device__ int   g_tok[NEXP][NTOK];
__device__ float g_wt [NEXP][NTOK];
// activation scratch: per expert, up to NTOK rows of IDIM (silu(x@w1)*(x@w3))
__device__ float g_act[(size_t)NEXP * NTOK * IDIM];

// ---------------------------------------------------------------------------
// Kernel 0: zero the output accumulator region + expert counters
// ---------------------------------------------------------------------------
__global__ void zero_kernel(float* __restrict__ out, size_t n) {
    size_t i = (size_t)blockIdx.x * blockDim.x + threadIdx.x;
    if (i < n) out[i] = 0.0f;
    if (i < NEXP) g_cnt[i] = 0;
}

// ---------------------------------------------------------------------------
// Kernel 1: router. One block (256 thr = 8 warps) per token.
// Computes logits, writes them, does top-2 + softmax, appends token to the
// two selected experts' lists.
// ---------------------------------------------------------------------------
__global__ void router_kernel(const float* __restrict__ x,
                              const float* __restrict__ gw,
                              float* __restrict__ logits_out) {
    int t = blockIdx.x;
    __shared__ float xs[HDIM];
    __shared__ float lg[NEXP];
    int tid = threadIdx.x;
    for (int i = tid; i < HDIM; i += 256) xs[i] = x[(size_t)t * HDIM + i];
    __syncthreads();

    int w = tid >> 5, lane = tid & 31;   // warp w -> expert w
    float s = 0.f;
    for (int k = lane; k < HDIM; k += 32) s += xs[k] * gw[k * NEXP + w];
    #pragma unroll
    for (int o = 16; o; o >>= 1) s += __shfl_xor_sync(0xffffffffu, s, o);
    if (lane == 0) lg[w] = s;
    __syncthreads();

    if (tid == 0) {
        #pragma unroll
        for (int e = 0; e < NEXP; e++) logits_out[(size_t)t * NEXP + e] = lg[e];
        // top-1 (first occurrence on ties, matching jax.lax.top_k)
        int b0 = 0; float v0 = lg[0];
        #pragma unroll
        for (int e = 1; e < NEXP; e++) if (lg[e] > v0) { v0 = lg[e]; b0 = e; }
        // top-2
        int b1 = -1; float v1 = -INFINITY;
        #pragma unroll
        for (int e = 0; e < NEXP; e++)
            if (e != b0 && lg[e] > v1) { v1 = lg[e]; b1 = e; }
        // softmax over {v0, v1} (v0 >= v1)
        float p1  = expf(v1 - v0);
        float inv = 1.0f / (1.0f + p1);
        float w0 = inv, w1 = p1 * inv;
        int p = atomicAdd(&g_cnt[b0], 1);
        g_tok[b0][p] = t; g_wt[b0][p] = w0;
        int q = atomicAdd(&g_cnt[b1], 1);
        g_tok[b1][q] = t; g_wt[b1][q] = w1;
    }
}

// ---------------------------------------------------------------------------
// Kernel 2: up-projection. Per expert e, gathered-A GEMM:
//   G[m, n] = silu(x[tok_m] . w1[e][:,n]) * (x[tok_m] . w3[e][:,n])
// Tiles: 64(M) x 64(N) x 16(K), 256 threads, 4x4 micro-tile, dual B operand.
// ---------------------------------------------------------------------------
__global__ __launch_bounds__(256, 2)
void ffn1_kernel(const float* __restrict__ x,
                 const float* __restrict__ w1,
                 const float* __restrict__ w3) {
    int e   = blockIdx.z;
    int cnt = g_cnt[e];
    int m0  = blockIdx.y * 64;
    if (m0 >= cnt) return;
    int n0  = blockIdx.x * 64;

    __shared__ float Xs [16][64];
    __shared__ float W1s[16][64];
    __shared__ float W3s[16][64];

    int tid = threadIdx.x;
    // A-load mapping: 64 rows x 16 k, float4 along k
    int lm = tid & 63, lk = (tid >> 6) << 2;
    int row = m0 + lm;
    int tok = (row < cnt) ? g_tok[e][row] : g_tok[e][0];
    const float* xrow = x + (size_t)tok * HDIM;
    // B-load mapping: 16 k-rows x 64 n, float4 along n
    int bk = tid >> 4, bn = (tid & 15) << 2;
    const float* W1p = w1 + (size_t)e * HDIM * IDIM;
    const float* W3p = w3 + (size_t)e * HDIM * IDIM;

    int ty = tid >> 4, tx = tid & 15;   // compute mapping: 16x16 threads
    float acc1[4][4] = {{0}}, acc3[4][4] = {{0}};

    for (int k0 = 0; k0 < HDIM; k0 += 16) {
        float4 xa = *reinterpret_cast<const float4*>(xrow + k0 + lk);
        Xs[lk + 0][lm] = xa.x; Xs[lk + 1][lm] = xa.y;
        Xs[lk + 2][lm] = xa.z; Xs[lk + 3][lm] = xa.w;
        size_t boff = (size_t)(k0 + bk) * IDIM + n0 + bn;
        *reinterpret_cast<float4*>(&W1s[bk][bn]) =
            *reinterpret_cast<const float4*>(W1p + boff);
        *reinterpret_cast<float4*>(&W3s[bk][bn]) =
            *reinterpret_cast<const float4*>(W3p + boff);
        __syncthreads();
        #pragma unroll
        for (int kk = 0; kk < 16; kk++) {
            float4 av  = *reinterpret_cast<const float4*>(&Xs [kk][ty << 2]);
            float4 b1v = *reinterpret_cast<const float4*>(&W1s[kk][tx << 2]);
            float4 b3v = *reinterpret_cast<const float4*>(&W3s[kk][tx << 2]);
            float a[4]  = {av.x, av.y, av.z, av.w};
            float b1[4] = {b1v.x, b1v.y, b1v.z, b1v.w};
            float b3[4] = {b3v.x, b3v.y, b3v.z, b3v.w};
            #pragma unroll
            for (int i = 0; i < 4; i++)
                #pragma unroll
                for (int j = 0; j < 4; j++) {
                    acc1[i][j] = fmaf(a[i], b1[j], acc1[i][j]);
                    acc3[i][j] = fmaf(a[i], b3[j], acc3[i][j]);
                }
        }
        __syncthreads();
    }

    float* G = g_act + ((size_t)e * NTOK + m0) * IDIM;
    #pragma unroll
    for (int i = 0; i < 4; i++) {
        int r = (ty << 2) + i;
        if (m0 + r < cnt) {
            #pragma unroll
            for (int j = 0; j < 4; j++) {
                float v   = acc1[i][j];
                float sig = 1.0f / (1.0f + expf(-v));
                G[(size_t)r * IDIM + n0 + (tx << 2) + j] = v * sig * acc3[i][j];
            }
        }
    }
}

// ---------------------------------------------------------------------------
// Kernel 3: down-projection. Per expert e:
//   out[tok_m, n] += wt_m * (G[m, :] . w2[e][:, n])
// Same tiling. atomicAdd scatter (exactly 2 commutative adds per element).
// ---------------------------------------------------------------------------
__global__ __launch_bounds__(256, 2)
void ffn2_kernel(const float* __restrict__ w2, float* __restrict__ out) {
    int e   = blockIdx.z;
    int cnt = g_cnt[e];
    int m0  = blockIdx.y * 64;
    if (m0 >= cnt) return;
    int n0  = blockIdx.x * 64;

    __shared__ float As[16][64];
    __shared__ float Bs[16][64];

    int tid = threadIdx.x;
    int lm = tid & 63, lk = (tid >> 6) << 2;
    int row = m0 + lm;
    bool arow_ok = (row < cnt);
    const float* arow = g_act + ((size_t)e * NTOK + row) * IDIM;
    int bk = tid >> 4, bn = (tid & 15) << 2;
    const float* W2p = w2 + (size_t)e * IDIM * HDIM;

    int ty = tid >> 4, tx = tid & 15;
    float acc[4][4] = {{0}};

    for (int k0 = 0; k0 < IDIM; k0 += 16) {
        float4 av;
        if (arow_ok) av = *reinterpret_cast<const float4*>(arow + k0 + lk);
        else         av = make_float4(0.f, 0.f, 0.f, 0.f);
        As[lk + 0][lm] = av.x; As[lk + 1][lm] = av.y;
        As[lk + 2][lm] = av.z; As[lk + 3][lm] = av.w;
        *reinterpret_cast<float4*>(&Bs[bk][bn]) =
            *reinterpret_cast<const float4*>(W2p + (size_t)(k0 + bk) * HDIM + n0 + bn);
        __syncthreads();
        #pragma unroll
        for (int kk = 0; kk < 16; kk++) {
            float4 a4 = *reinterpret_cast<const float4*>(&As[kk][ty << 2]);
            float4 b4 = *reinterpret_cast<const float4*>(&Bs[kk][tx << 2]);
            float a[4] = {a4.x, a4.y, a4.z, a4.w};
            float b[4] = {b4.x, b4.y, b4.z, b4.w};
            #pragma unroll
            for (int i = 0; i < 4; i++)
                #pragma unroll
                for (int j = 0; j < 4; j++)
                    acc[i][j] = fmaf(a[i], b[j], acc[i][j]);
        }
        __syncthreads();
    }

    #pragma unroll
    for (int i = 0; i < 4; i++) {
        int r = (ty << 2) + i;
        int rm = m0 + r;
        if (rm < cnt) {
            int   tok = g_tok[e][rm];
            float wgt = g_wt [e][rm];
            float* orow = out + (size_t)tok * HDIM + n0 + (tx << 2);
            #pragma unroll
            for (int j = 0; j < 4; j++)
                atomicAdd(&orow[j], wgt * acc[i][j]);
        }
    }
}

// ---------------------------------------------------------------------------
extern "C" void kernel_launch(void* const* d_in, const int* in_sizes, int n_in,
                              void* d_out, int out_size) {
    const float* x  = (const float*)d_in[0];  // hidden_states [2,2048,1024]
    const float* gw = (const float*)d_in[1];  // gate_w [1024,8]
    const float* w1 = (const float*)d_in[2];  // [8,1024,3584]
    const float* w3 = (const float*)d_in[3];  // [8,1024,3584]
    const float* w2 = (const float*)d_in[4];  // [8,3584,1024]
    float* out = (float*)d_out;
    // output layout: final_hidden_state [2,2048,1024] then router_logits [2,2048,8]
    float* logits = out + ((size_t)out_size - (size_t)NTOK * NEXP);

    size_t nzero = (size_t)NTOK * HDIM;
    zero_kernel<<<(unsigned)((nzero + 255) / 256), 256>>>(out, nzero);
    router_kernel<<<NTOK, 256>>>(x, gw, logits);

    dim3 g1(IDIM / 64, NTOK / 64, NEXP);
    ffn1_kernel<<<g1, 256>>>(x, w1, w3);

    dim3 g2(HDIM / 64, NTOK / 64, NEXP);
    ffn2_kernel<<<g2, 256>>>(w2, out);
}

// round 3
// speedup vs baseline: 3.4896x; 3.4896x over previous
#include <cuda_runtime.h>
#include <math.h>
#include <stdint.h>

#define NTOK 4096      // B*S
#define HDIM 1024
#define IDIM 3584
#define NEXP 8

// ---------------- device scratch (no allocs) ----------------
__device__ int   g_cnt[NEXP];
__device__ int   g_tok[NEXP][NTOK];
__device__ float g_wt [NEXP][NTOK];
__device__ int   g_texp [NTOK * 2];
__device__ int   g_tslot[NTOK * 2];
__device__ float g_act [(size_t)NEXP * NTOK * IDIM];   // silu(x w1)*(x w3)
__device__ float g_part[(size_t)NEXP * NTOK * HDIM];   // weight-folded expert outs

// ---------------- helpers ----------------
__device__ __forceinline__ uint32_t smem_u32(const void* p) {
    uint32_t a;
    asm("{ .reg .u64 t; cvta.to.shared.u64 t, %1; cvt.u32.u64 %0, t; }" : "=r"(a) : "l"(p));
    return a;
}
__device__ __forceinline__ uint32_t f2tf(float f) {
    uint32_t r; asm("cvt.rna.tf32.f32 %0, %1;" : "=r"(r) : "f"(f)); return r;
}
__device__ __forceinline__ void sts_tf4(uint32_t addr, float4 v) {
    uint32_t a = f2tf(v.x), b = f2tf(v.y), c = f2tf(v.z), d = f2tf(v.w);
    asm volatile("st.shared.v4.b32 [%0], {%1,%2,%3,%4};"
                 :: "r"(addr), "r"(a), "r"(b), "r"(c), "r"(d) : "memory");
}
// m16n8k8 tf32 warp MMA (baseline PTX ISA — works on plain sm_103 target)
__device__ __forceinline__ void mma8(float* d, uint32_t a0, uint32_t a1, uint32_t a2,
                                     uint32_t a3, uint32_t b0, uint32_t b1) {
    asm volatile(
        "mma.sync.aligned.m16n8k8.row.col.f32.tf32.tf32.f32 "
        "{%0,%1,%2,%3},{%4,%5,%6,%7},{%8,%9},{%0,%1,%2,%3};"
        : "+f"(d[0]), "+f"(d[1]), "+f"(d[2]), "+f"(d[3])
        : "r"(a0), "r"(a1), "r"(a2), "r"(a3), "r"(b0), "r"(b1));
}

// smem strides in 32-bit words
#define ASTR 36    // 128 rows x 32 k (+4 pad)  -> conflict-free frag loads & v4 stores
#define BSTR 136   // 32 k-rows x 128 n (+8 pad)
#define A_WORDS  (128 * ASTR)   // 4608
#define B_WORDS  (32 * BSTR)    // 4352

// ---------------------------------------------------------------------------
__global__ void zero_kernel() { if (threadIdx.x < NEXP) g_cnt[threadIdx.x] = 0; }

// ---------------------------------------------------------------------------
__global__ void router_kernel(const float* __restrict__ x,
                              const float* __restrict__ gw,
                              float* __restrict__ logits_out) {
    int t = blockIdx.x;
    __shared__ float xs[HDIM];
    __shared__ float lg[NEXP];
    int tid = threadIdx.x;
    for (int i = tid; i < HDIM; i += 256) xs[i] = x[(size_t)t * HDIM + i];
    __syncthreads();
    int w = tid >> 5, lane = tid & 31;
    float s = 0.f;
    for (int k = lane; k < HDIM; k += 32) s += xs[k] * gw[k * NEXP + w];
    #pragma unroll
    for (int o = 16; o; o >>= 1) s += __shfl_xor_sync(0xffffffffu, s, o);
    if (lane == 0) lg[w] = s;
    __syncthreads();
    if (tid == 0) {
        #pragma unroll
        for (int e = 0; e < NEXP; e++) logits_out[(size_t)t * NEXP + e] = lg[e];
        int b0 = 0; float v0 = lg[0];
        #pragma unroll
        for (int e = 1; e < NEXP; e++) if (lg[e] > v0) { v0 = lg[e]; b0 = e; }
        int b1 = -1; float v1 = -INFINITY;
        #pragma unroll
        for (int e = 0; e < NEXP; e++) if (e != b0 && lg[e] > v1) { v1 = lg[e]; b1 = e; }
        float p1  = expf(v1 - v0);
        float inv = 1.0f / (1.0f + p1);
        int p = atomicAdd(&g_cnt[b0], 1);
        g_tok[b0][p] = t; g_wt[b0][p] = inv;
        int q = atomicAdd(&g_cnt[b1], 1);
        g_tok[b1][q] = t; g_wt[b1][q] = p1 * inv;
        g_texp[2 * t] = b0;  g_tslot[2 * t] = p;
        g_texp[2 * t + 1] = b1; g_tslot[2 * t + 1] = q;
    }
}

// ---------------------------------------------------------------------------
// FFN1: per expert, D1 = X.w1, D3 = X.w3 (tf32 mma.sync), G = silu(D1)*D3.
// CTA tile 128x128x32; 8 warps (2Mx4N), warp tile 64x32; A frags shared by both B.
// ---------------------------------------------------------------------------
__global__ __launch_bounds__(256, 1)
void ffn1_mma(const float* __restrict__ x,
              const float* __restrict__ w1,
              const float* __restrict__ w3) {
    extern __shared__ uint32_t sm[];
    __shared__ int toks[128];
    const int tid = threadIdx.x;
    const int e   = blockIdx.z;
    const int cnt = g_cnt[e];
    const int m0  = blockIdx.y * 128;
    if (m0 >= cnt) return;
    const int n0  = blockIdx.x * 128;

    if (tid < 128) {
        int r = m0 + tid;
        toks[tid] = (r < cnt) ? g_tok[e][r] : g_tok[e][0];
    }
    __syncthreads();
    uint32_t sb = smem_u32(sm);

    // staging thread mapping
    const int fa = tid & 7,  ma = tid >> 3;    // A: 8 float4 per row, 32 row-groups
    const int fb = tid & 31, kb = tid >> 5;    // B: 32 float4 per k-row, 8 k-groups
    const float* ap[4];
    #pragma unroll
    for (int s = 0; s < 4; s++)
        ap[s] = x + (size_t)toks[ma + 32 * s] * HDIM + fa * 4;
    const float* W1 = w1 + (size_t)e * HDIM * IDIM + n0 + fb * 4;
    const float* W3 = w3 + (size_t)e * HDIM * IDIM + n0 + fb * 4;

    // compute mapping
    const int wid = tid >> 5, lane = tid & 31;
    const int wm = (wid >> 2) * 64, wn = (wid & 3) * 32;
    const int g = lane >> 2, t = lane & 3;

    float acc1[4][4][4], acc3[4][4][4];
    #pragma unroll
    for (int i = 0; i < 4; i++)
        #pragma unroll
        for (int j = 0; j < 4; j++)
            #pragma unroll
            for (int c = 0; c < 4; c++) { acc1[i][j][c] = 0.f; acc3[i][j][c] = 0.f; }

    float4 rA[4], rB1[4], rB3[4];
    #pragma unroll
    for (int s = 0; s < 4; s++) {
        rA[s]  = *(const float4*)(ap[s]);
        rB1[s] = *(const float4*)(W1 + (size_t)(kb + 8 * s) * IDIM);
        rB3[s] = *(const float4*)(W3 + (size_t)(kb + 8 * s) * IDIM);
    }

    const int NC = HDIM / 32;
    for (int it = 0; it < NC; it++) {
        int p = it & 1;
        uint32_t aoff  = sb + (p * A_WORDS) * 4;
        uint32_t b1off = sb + (2 * A_WORDS + p * B_WORDS) * 4;
        uint32_t b3off = sb + (2 * A_WORDS + 2 * B_WORDS + p * B_WORDS) * 4;
        #pragma unroll
        for (int s = 0; s < 4; s++) {
            sts_tf4(aoff  + ((ma + 32 * s) * ASTR + fa * 4) * 4, rA[s]);
            sts_tf4(b1off + ((kb + 8 * s) * BSTR + fb * 4) * 4, rB1[s]);
            sts_tf4(b3off + ((kb + 8 * s) * BSTR + fb * 4) * 4, rB3[s]);
        }
        __syncthreads();
        if (it + 1 < NC) {
            int k0 = (it + 1) * 32;
            #pragma unroll
            for (int s = 0; s < 4; s++) {
                rA[s]  = *(const float4*)(ap[s] + k0);
                rB1[s] = *(const float4*)(W1 + (size_t)(k0 + kb + 8 * s) * IDIM);
                rB3[s] = *(const float4*)(W3 + (size_t)(k0 + kb + 8 * s) * IDIM);
            }
        }
        const uint32_t* As  = sm + p * A_WORDS;
        const uint32_t* B1s = sm + 2 * A_WORDS + p * B_WORDS;
        const uint32_t* B3s = sm + 2 * A_WORDS + 2 * B_WORDS + p * B_WORDS;
        #pragma unroll
        for (int ks = 0; ks < 4; ks++) {
            uint32_t af[4][4];
            #pragma unroll
            for (int mt = 0; mt < 4; mt++) {
                int m = wm + mt * 16;
                af[mt][0] = As[(m + g)     * ASTR + ks * 8 + t];
                af[mt][1] = As[(m + g + 8) * ASTR + ks * 8 + t];
                af[mt][2] = As[(m + g)     * ASTR + ks * 8 + t + 4];
                af[mt][3] = As[(m + g + 8) * ASTR + ks * 8 + t + 4];
            }
            #pragma unroll
            for (int nt = 0; nt < 4; nt++) {
                int n = wn + nt * 8;
                uint32_t b10 = B1s[(ks * 8 + t)     * BSTR + n + g];
                uint32_t b11 = B1s[(ks * 8 + t + 4) * BSTR + n + g];
                uint32_t b30 = B3s[(ks * 8 + t)     * BSTR + n + g];
                uint32_t b31 = B3s[(ks * 8 + t + 4) * BSTR + n + g];
                #pragma unroll
                for (int mt = 0; mt < 4; mt++) {
                    mma8(acc1[mt][nt], af[mt][0], af[mt][1], af[mt][2], af[mt][3], b10, b11);
                    mma8(acc3[mt][nt], af[mt][0], af[mt][1], af[mt][2], af[mt][3], b30, b31);
                }
            }
        }
    }

    // epilogue: G = silu(D1) * D3
    #pragma unroll
    for (int mt = 0; mt < 4; mt++) {
        int r0 = wm + mt * 16 + g;
        int r1 = r0 + 8;
        bool ok0 = (m0 + r0) < cnt, ok1 = (m0 + r1) < cnt;
        float* G0 = g_act + ((size_t)e * NTOK + m0 + r0) * IDIM + n0;
        float* G1 = g_act + ((size_t)e * NTOK + m0 + r1) * IDIM + n0;
        #pragma unroll
        for (int nt = 0; nt < 4; nt++) {
            int cc = wn + nt * 8 + 2 * t;
            if (ok0) {
                float v0 = acc1[mt][nt][0], v1 = acc1[mt][nt][1];
                float2 o;
                o.x = v0 / (1.0f + __expf(-v0)) * acc3[mt][nt][0];
                o.y = v1 / (1.0f + __expf(-v1)) * acc3[mt][nt][1];
                *(float2*)(G0 + cc) = o;
            }
            if (ok1) {
                float v2 = acc1[mt][nt][2], v3 = acc1[mt][nt][3];
                float2 o;
                o.x = v2 / (1.0f + __expf(-v2)) * acc3[mt][nt][2];
                o.y = v3 / (1.0f + __expf(-v3)) * acc3[mt][nt][3];
                *(float2*)(G1 + cc) = o;
            }
        }
    }
}

// ---------------------------------------------------------------------------
// FFN2: P = wt * (G . w2) into g_part (weight folded, no atomics)
// ---------------------------------------------------------------------------
__global__ __launch_bounds__(256, 1)
void ffn2_mma(const float* __restrict__ w2) {
    extern __shared__ uint32_t sm[];
    __shared__ float wts[128];
    const int tid = threadIdx.x;
    const int e   = blockIdx.z;
    const int cnt = g_cnt[e];
    const int m0  = blockIdx.y * 128;
    if (m0 >= cnt) return;
    const int n0  = blockIdx.x * 128;

    if (tid < 128) {
        int r = m0 + tid;
        wts[tid] = (r < cnt) ? g_wt[e][r] : 0.0f;
    }
    __syncthreads();
    uint32_t sb = smem_u32(sm);

    const int fa = tid & 7,  ma = tid >> 3;
    const int fb = tid & 31, kb = tid >> 5;
    const float* A0 = g_act + ((size_t)e * NTOK + m0) * IDIM;
    const float* ap[4];
    #pragma unroll
    for (int s = 0; s < 4; s++)
        ap[s] = A0 + (size_t)(ma + 32 * s) * IDIM + fa * 4;
    const float* W = w2 + (size_t)e * IDIM * HDIM + n0 + fb * 4;

    const int wid = tid >> 5, lane = tid & 31;
    const int wm = (wid >> 2) * 64, wn = (wid & 3) * 32;
    const int g = lane >> 2, t = lane & 3;

    float acc[4][4][4];
    #pragma unroll
    for (int i = 0; i < 4; i++)
        #pragma unroll
        for (int j = 0; j < 4; j++)
            #pragma unroll
            for (int c = 0; c < 4; c++) acc[i][j][c] = 0.f;

    float4 rA[4], rB[4];
    #pragma unroll
    for (int s = 0; s < 4; s++) {
        rA[s] = *(const float4*)(ap[s]);
        rB[s] = *(const float4*)(W + (size_t)(kb + 8 * s) * HDIM);
    }

    const int NC = IDIM / 32;   // 112
    for (int it = 0; it < NC; it++) {
        int p = it & 1;
        uint32_t aoff = sb + (p * A_WORDS) * 4;
        uint32_t boff = sb + (2 * A_WORDS + p * B_WORDS) * 4;
        #pragma unroll
        for (int s = 0; s < 4; s++) {
            sts_tf4(aoff + ((ma + 32 * s) * ASTR + fa * 4) * 4, rA[s]);
            sts_tf4(boff + ((kb + 8 * s) * BSTR + fb * 4) * 4, rB[s]);
        }
        __syncthreads();
        if (it + 1 < NC) {
            int k0 = (it + 1) * 32;
            #pragma unroll
            for (int s = 0; s < 4; s++) {
                rA[s] = *(const float4*)(ap[s] + k0);
                rB[s] = *(const float4*)(W + (size_t)(k0 + kb + 8 * s) * HDIM);
            }
        }
        const uint32_t* As = sm + p * A_WORDS;
        const uint32_t* Bs = sm + 2 * A_WORDS + p * B_WORDS;
        #pragma unroll
        for (int ks = 0; ks < 4; ks++) {
            uint32_t af[4][4];
            #pragma unroll
            for (int mt = 0; mt < 4; mt++) {
                int m = wm + mt * 16;
                af[mt][0] = As[(m + g)     * ASTR + ks * 8 + t];
                af[mt][1] = As[(m + g + 8) * ASTR + ks * 8 + t];
                af[mt][2] = As[(m + g)     * ASTR + ks * 8 + t + 4];
                af[mt][3] = As[(m + g + 8) * ASTR + ks * 8 + t + 4];
            }
            #pragma unroll
            for (int nt = 0; nt < 4; nt++) {
                int n = wn + nt * 8;
                uint32_t b0 = Bs[(ks * 8 + t)     * BSTR + n + g];
                uint32_t b1 = Bs[(ks * 8 + t + 4) * BSTR + n + g];
                #pragma unroll
                for (int mt = 0; mt < 4; mt++)
                    mma8(acc[mt][nt], af[mt][0], af[mt][1], af[mt][2], af[mt][3], b0, b1);
            }
        }
    }

    #pragma unroll
    for (int mt = 0; mt < 4; mt++) {
        int r0 = wm + mt * 16 + g;
        int r1 = r0 + 8;
        bool ok0 = (m0 + r0) < cnt, ok1 = (m0 + r1) < cnt;
        float w0 = wts[r0 & 127], w1v = wts[r1 & 127];
        float* P0 = g_part + ((size_t)e * NTOK + m0 + r0) * HDIM + n0;
        float* P1 = g_part + ((size_t)e * NTOK + m0 + r1) * HDIM + n0;
        #pragma unroll
        for (int nt = 0; nt < 4; nt++) {
            int cc = wn + nt * 8 + 2 * t;
            if (ok0) {
                float2 o = make_float2(w0 * acc[mt][nt][0], w0 * acc[mt][nt][1]);
                *(float2*)(P0 + cc) = o;
            }
            if (ok1) {
                float2 o = make_float2(w1v * acc[mt][nt][2], w1v * acc[mt][nt][3]);
                *(float2*)(P1 + cc) = o;
            }
        }
    }
}

// ---------------------------------------------------------------------------
__global__ void combine_kernel(float* __restrict__ out) {
    int t  = blockIdx.x;
    int e0 = g_texp[2 * t],     s0 = g_tslot[2 * t];
    int e1 = g_texp[2 * t + 1], s1 = g_tslot[2 * t + 1];
    const float4* P0 = (const float4*)(g_part + ((size_t)e0 * NTOK + s0) * HDIM);
    const float4* P1 = (const float4*)(g_part + ((size_t)e1 * NTOK + s1) * HDIM);
    float4* O = (float4*)(out + (size_t)t * HDIM);
    int i = threadIdx.x;
    float4 a = P0[i], b = P1[i];
    O[i] = make_float4(a.x + b.x, a.y + b.y, a.z + b.z, a.w + b.w);
}

// ---------------------------------------------------------------------------
extern "C" void kernel_launch(void* const* d_in, const int* in_sizes, int n_in,
                              void* d_out, int out_size) {
    const float* x  = (const float*)d_in[0];
    const float* gw = (const float*)d_in[1];
    const float* w1 = (const float*)d_in[2];
    const float* w3 = (const float*)d_in[3];
    const float* w2 = (const float*)d_in[4];
    float* out = (float*)d_out;
    float* logits = out + ((size_t)out_size - (size_t)NTOK * NEXP);

    const int SMEM1 = (2 * A_WORDS + 4 * B_WORDS) * 4;  // 106496 B
    const int SMEM2 = (2 * A_WORDS + 2 * B_WORDS) * 4;  //  71680 B
    cudaFuncSetAttribute(ffn1_mma, cudaFuncAttributeMaxDynamicSharedMemorySize, SMEM1);
    cudaFuncSetAttribute(ffn2_mma, cudaFuncAttributeMaxDynamicSharedMemorySize, SMEM2);

    zero_kernel<<<1, 32>>>();
    router_kernel<<<NTOK, 256>>>(x, gw, logits);

    dim3 g1(IDIM / 128, NTOK / 128, NEXP);
    ffn1_mma<<<g1, 256, SMEM1>>>(x, w1, w3);

    dim3 g2(HDIM / 128, NTOK / 128, NEXP);
    ffn2_mma<<<g2, 256, SMEM2>>>(w2);

    combine_kernel<<<NTOK, 256>>>(out);
}